// round 8
// baseline (speedup 1.0000x reference)
#include <cuda_runtime.h>
#include <cstdint>

// ---------------- problem constants ----------------
#define SEQ    2048
#define DIMN   1024
#define BATCH  2
#define MR     4096            // BATCH*SEQ

// ---------------- GEMM tiling ----------------
#define BM 128
#define BN 128
#define BK 16                  // 16 floats; rows packed [hi 64B | lo 64B] = 128B
#define NTHREADS 256

#define TILEB  (BM * 128)              // 16384 B per operand tile (hi+lo packed)
#define STAGE  (2 * TILEB)             // A tile + B tile = 32768 B
#define NSTAGE 3
#define SMEM_BYTES (NSTAGE * STAGE)    // 98304 B -> 2 CTAs/SM

// ---------------- scratch (__device__ globals; no allocs allowed) ----------------
static __device__ float g_xh[MR * DIMN],  g_xl[MR * DIMN];
static __device__ float g_wh[4][DIMN * DIMN], g_wl[4][DIMN * DIMN]; // q,k,v,o
static __device__ float g_qh[MR * DIMN],  g_ql[MR * DIMN];
static __device__ float g_kh[MR * DIMN],  g_kl[MR * DIMN];
static __device__ float g_vTh[MR * DIMN], g_vTl[MR * DIMN];         // [B][D][S]
static __device__ float g_s[BATCH * SEQ * SEQ];
static __device__ float g_p[BATCH * SEQ * SEQ];                     // tf32-rounded P
static __device__ float g_o[MR * DIMN];                             // tf32-rounded O

// ---------------- helpers ----------------
__device__ __forceinline__ uint32_t smem_u32(const void* p) {
    uint32_t a;
    asm("{ .reg .u64 t; cvta.to.shared.u64 t, %1; cvt.u32.u64 %0, t; }"
        : "=r"(a) : "l"(p));
    return a;
}

__device__ __forceinline__ float f2tf32(float x) {
    uint32_t u;
    asm("cvt.rna.tf32.f32 %0, %1;" : "=r"(u) : "f"(x));
    return __uint_as_float(u);
}

__device__ __forceinline__ void cp16(uint32_t saddr, const float* g) {
    asm volatile("cp.async.cg.shared.global [%0], [%1], 16;"
                 :: "r"(saddr), "l"(g) : "memory");
}

__device__ __forceinline__ void ldsm4(uint32_t* r, uint32_t addr) {
    asm volatile("ldmatrix.sync.aligned.m8n8.x4.shared.b16 {%0,%1,%2,%3}, [%4];"
                 : "=r"(r[0]), "=r"(r[1]), "=r"(r[2]), "=r"(r[3])
                 : "r"(addr));
}

__device__ __forceinline__ void mma_tf32(float* d, const uint32_t* a,
                                         uint32_t b0, uint32_t b1) {
    asm volatile(
        "mma.sync.aligned.m16n8k8.row.col.f32.tf32.tf32.f32 "
        "{%0,%1,%2,%3}, {%4,%5,%6,%7}, {%8,%9}, {%0,%1,%2,%3};"
        : "+f"(d[0]), "+f"(d[1]), "+f"(d[2]), "+f"(d[3])
        : "r"(a[0]), "r"(a[1]), "r"(a[2]), "r"(a[3]), "r"(b0), "r"(b1));
}

__device__ __forceinline__ uint32_t sw128(uint32_t x) {
    return x ^ ((x >> 3) & 0x70);   // 128B-row xor swizzle
}

// ----------------------------------------------------------------------------
// Multi-pass tf32 GEMM via mma.sync:  C[M,N] = A[M,K] @ B[N,K]^T
// NPASS = 3: A = Ah+Al, B = Bh+Bl, terms hh + lh + hl (tf32x3 ~ fp32)
// NPASS = 2: A = Ah only,          terms hh + hl      (A-lo dropped)
// EPI: 0 = plain fp32 store (+optional bias)        (QK scores, final output)
//      1 = split store hi/lo (+optional bias)       (q/k projections)
//      2 = split store TRANSPOSED [b][n][t] (+bias) (v projection -> v^T)
//      3 = tf32-rounded single store                (PV -> O)
// Lo halves live at sw128(raw + 64): pre-swizzle offset, so the XOR keeps
// every address inside its own 128B row (sw128(x)^64, never a carry).
// ----------------------------------------------------------------------------
template <int NPASS, int EPI>
__global__ void __launch_bounds__(NTHREADS, 2)
gemm_mp(const float* __restrict__ Ah, const float* __restrict__ Al,
        const float* __restrict__ Bh, const float* __restrict__ Bl,
        const float* __restrict__ bias,
        float* __restrict__ C0, float* __restrict__ C1,
        int M, int N, int K,
        long long sA, long long sB, long long sC)
{
    extern __shared__ char dsmem[];
    const uint32_t sbase = smem_u32(dsmem);

    const int tid  = threadIdx.x;
    const int lane = tid & 31;
    const int wid  = tid >> 5;
    const int wm   = wid >> 2;        // 0..1 (m warp row)
    const int wn   = wid & 3;         // 0..3 (n warp col)

    const int m0 = blockIdx.y * BM;
    const int n0 = blockIdx.x * BN;
    const int bz = blockIdx.z;

    const float* pAh = Ah + (long long)bz * sA;
    const float* pAl = Al + (long long)bz * sA;
    const float* pBh = Bh + (long long)bz * sB;
    const float* pBl = Bl + (long long)bz * sB;

    // ---- cp.async slots: 512 16B hi-chunks per tile; each thread owns 2
    uint32_t c_hi[2];   // swizzled smem offset of hi chunk
    uint32_t c_lo[2];   // swizzled smem offset of lo chunk (raw + 64)
    int      a_g[2];    // gmem float offset (A)
    int      b_g[2];    // gmem float offset (B)
#pragma unroll
    for (int j = 0; j < 2; j++) {
        int c   = tid + j * NTHREADS;    // 0..511
        int row = c >> 2;                // 0..127
        int cc  = c & 3;                 // 16B chunk within 64B half
        uint32_t raw = (uint32_t)(row * 128 + cc * 16);
        c_hi[j] = sw128(raw);
        c_lo[j] = sw128(raw + 64);
        a_g[j]  = (m0 + row) * K + cc * 4;
        b_g[j]  = (n0 + row) * K + cc * 4;
    }

    auto load_tile = [&](int kt, int s) {
        const int k0 = kt * BK;
        const uint32_t stA = sbase + (uint32_t)s * STAGE;
        const uint32_t stB = stA + TILEB;
#pragma unroll
        for (int j = 0; j < 2; j++) {
            cp16(stA + c_hi[j], pAh + a_g[j] + k0);
            if (NPASS == 3)
                cp16(stA + c_lo[j], pAl + a_g[j] + k0);
            cp16(stB + c_hi[j], pBh + b_g[j] + k0);
            cp16(stB + c_lo[j], pBl + b_g[j] + k0);
        }
        asm volatile("cp.async.commit_group;" ::: "memory");
    };

    // ---- ldmatrix address components
    const int piece = lane >> 3;
    const int pr    = lane & 7;

    int a_row[4];
#pragma unroll
    for (int mt = 0; mt < 4; mt++)
        a_row[mt] = (wm * 64 + mt * 16 + ((piece & 1) << 3) + pr) * 128;
    int b_row[2];
#pragma unroll
    for (int nt2 = 0; nt2 < 2; nt2++)
        b_row[nt2] = (wn * 32 + nt2 * 16 + ((piece >> 1) << 3) + pr) * 128;
    const int a_ch = (piece >> 1) * 16;   // + ks*32 (hi); raw+64 for lo
    const int b_ch = (piece & 1) * 16;

    float acc[4][4][4];
#pragma unroll
    for (int i = 0; i < 4; i++)
#pragma unroll
        for (int j = 0; j < 4; j++)
#pragma unroll
            for (int r = 0; r < 4; r++) acc[i][j][r] = 0.0f;

    const int KT = K / BK;
    load_tile(0, 0);
    load_tile(1, 1);

    int s = 0, sp = 2;
    for (int kt = 0; kt < KT; kt++) {
        if (kt + 1 < KT)
            asm volatile("cp.async.wait_group 1;" ::: "memory");
        else
            asm volatile("cp.async.wait_group 0;" ::: "memory");
        __syncthreads();
        if (kt + 2 < KT) {
            load_tile(kt + 2, sp);
            if (++sp == NSTAGE) sp = 0;
        }

        const uint32_t stA = sbase + (uint32_t)s * STAGE;
        const uint32_t stB = stA + TILEB;
        if (++s == NSTAGE) s = 0;

#pragma unroll
        for (int ks = 0; ks < 2; ks++) {
            uint32_t fAh[4][4], fAl[4][4];
#pragma unroll
            for (int mt = 0; mt < 4; mt++) {
                uint32_t raw = (uint32_t)(a_row[mt] + ks * 32 + a_ch);
                ldsm4(fAh[mt], stA + sw128(raw));
                if (NPASS == 3) ldsm4(fAl[mt], stA + sw128(raw + 64));
            }
            uint32_t fBh[2][4], fBl[2][4];
#pragma unroll
            for (int nt2 = 0; nt2 < 2; nt2++) {
                uint32_t raw = (uint32_t)(b_row[nt2] + ks * 32 + b_ch);
                ldsm4(fBh[nt2], stB + sw128(raw));
                ldsm4(fBl[nt2], stB + sw128(raw + 64));
            }
#pragma unroll
            for (int mt = 0; mt < 4; mt++) {
#pragma unroll
                for (int nt = 0; nt < 4; nt++) {
                    const int nt2 = nt >> 1, h = (nt & 1) * 2;
                    float* d = acc[mt][nt];
                    mma_tf32(d, fAh[mt], fBh[nt2][h], fBh[nt2][h + 1]);
                    if (NPASS == 3)
                        mma_tf32(d, fAl[mt], fBh[nt2][h], fBh[nt2][h + 1]);
                    mma_tf32(d, fAh[mt], fBl[nt2][h], fBl[nt2][h + 1]);
                }
            }
        }
    }

    // ---- epilogue
    const int rbase = m0 + wm * 64 + (lane >> 2);
    const int cbase = n0 + wn * 32 + (lane & 3) * 2;

#pragma unroll
    for (int mt = 0; mt < 4; mt++) {
#pragma unroll
        for (int nt = 0; nt < 4; nt++) {
            const float* d = acc[mt][nt];
            const int col = cbase + nt * 8;
            const long long r0 = rbase + mt * 16;
            const long long r1 = r0 + 8;
            float b0f = 0.0f, b1f = 0.0f;
            if (bias) { b0f = bias[col]; b1f = bias[col + 1]; }

            if (EPI == 0) {
                float* C = C0 + (long long)bz * sC;
                *reinterpret_cast<float2*>(&C[r0 * N + col]) =
                    make_float2(d[0] + b0f, d[1] + b1f);
                *reinterpret_cast<float2*>(&C[r1 * N + col]) =
                    make_float2(d[2] + b0f, d[3] + b1f);
            } else if (EPI == 1) {
                float* Ch = C0 + (long long)bz * sC;
                float* Cl = C1 + (long long)bz * sC;
                float v00 = d[0] + b0f, v01 = d[1] + b1f;
                float v10 = d[2] + b0f, v11 = d[3] + b1f;
                float h00 = f2tf32(v00), h01 = f2tf32(v01);
                float h10 = f2tf32(v10), h11 = f2tf32(v11);
                *reinterpret_cast<float2*>(&Ch[r0 * N + col]) =
                    make_float2(h00, h01);
                *reinterpret_cast<float2*>(&Ch[r1 * N + col]) =
                    make_float2(h10, h11);
                *reinterpret_cast<float2*>(&Cl[r0 * N + col]) =
                    make_float2(f2tf32(v00 - h00), f2tf32(v01 - h01));
                *reinterpret_cast<float2*>(&Cl[r1 * N + col]) =
                    make_float2(f2tf32(v10 - h10), f2tf32(v11 - h11));
            } else if (EPI == 2) {  // v^T split store, layout [b][n][t]
#pragma unroll
                for (int e = 0; e < 4; e++) {
                    const long long mr = (e < 2) ? r0 : r1;
                    const int n = col + (e & 1);
                    const float v = d[e] + ((e & 1) ? b1f : b0f);
                    const long long bb = mr >> 11;      // SEQ rows per batch
                    const long long t  = mr & 2047;
                    const float h = f2tf32(v);
                    const long long idx = (bb * DIMN + n) * SEQ + t;
                    C0[idx] = h;
                    C1[idx] = f2tf32(v - h);
                }
            } else {  // EPI == 3: tf32-rounded single store
                float* C = C0 + (long long)bz * sC;
                *reinterpret_cast<float2*>(&C[r0 * N + col]) =
                    make_float2(f2tf32(d[0] + b0f), f2tf32(d[1] + b1f));
                *reinterpret_cast<float2*>(&C[r1 * N + col]) =
                    make_float2(f2tf32(d[2] + b0f), f2tf32(d[3] + b1f));
            }
        }
    }
}

// ----------------------------------------------------------------------------
// tf32 hi/lo split of external inputs (lo re-rounded to exact tf32)
// ----------------------------------------------------------------------------
__global__ void __launch_bounds__(256)
split_kernel(const float* __restrict__ src, float* __restrict__ hi,
             float* __restrict__ lo, int n4)
{
    const int i = blockIdx.x * 256 + threadIdx.x;
    if (i < n4) {
        float4 v = reinterpret_cast<const float4*>(src)[i];
        float4 h, l;
        h.x = f2tf32(v.x); l.x = f2tf32(v.x - h.x);
        h.y = f2tf32(v.y); l.y = f2tf32(v.y - h.y);
        h.z = f2tf32(v.z); l.z = f2tf32(v.z - h.z);
        h.w = f2tf32(v.w); l.w = f2tf32(v.w - h.w);
        reinterpret_cast<float4*>(hi)[i] = h;
        reinterpret_cast<float4*>(lo)[i] = l;
    }
}

// ----------------------------------------------------------------------------
// theta + softmax; emits tf32-rounded probabilities (lo dropped; PV is x2)
// theta = 0.5 + 0.2*sigmoid(x) + 0.15*tanh(x) + 0.1*relu(x)
// ----------------------------------------------------------------------------
__global__ void __launch_bounds__(256)
theta_softmax(const float* __restrict__ S, float* __restrict__ P)
{
    const long long ro = (long long)blockIdx.x * SEQ;
    const int tid  = threadIdx.x;
    const int lane = tid & 31;
    const int wid  = tid >> 5;
    __shared__ float red[8];

    float th[8];
    float mx = -1e30f;
#pragma unroll
    for (int j = 0; j < 8; j++) {
        float x = S[ro + tid + j * 256];
        float sg = 1.0f / (1.0f + __expf(-x));
        float t;
        asm("tanh.approx.f32 %0, %1;" : "=f"(t) : "f"(x));
        float v = 0.5f + 0.2f * sg + 0.15f * t + 0.1f * fmaxf(x, 0.0f);
        th[j] = v;
        mx = fmaxf(mx, v);
    }
#pragma unroll
    for (int o = 16; o > 0; o >>= 1)
        mx = fmaxf(mx, __shfl_xor_sync(0xFFFFFFFFu, mx, o));
    if (lane == 0) red[wid] = mx;
    __syncthreads();
    mx = red[0];
#pragma unroll
    for (int w = 1; w < 8; w++) mx = fmaxf(mx, red[w]);
    __syncthreads();

    float sum = 0.0f;
#pragma unroll
    for (int j = 0; j < 8; j++) {
        float e = __expf(th[j] - mx);
        th[j] = e;
        sum += e;
    }
#pragma unroll
    for (int o = 16; o > 0; o >>= 1)
        sum += __shfl_xor_sync(0xFFFFFFFFu, sum, o);
    if (lane == 0) red[wid] = sum;
    __syncthreads();
    sum = red[0];
#pragma unroll
    for (int w = 1; w < 8; w++) sum += red[w];

    const float inv = 1.0f / sum;
#pragma unroll
    for (int j = 0; j < 8; j++)
        P[ro + tid + j * 256] = f2tf32(th[j] * inv);
}

// ----------------------------------------------------------------------------
// launch — inputs: x, Wq, bq, Wk, bk, Wv, bv, Wo, bo
// ----------------------------------------------------------------------------
extern "C" void kernel_launch(void* const* d_in, const int* in_sizes, int n_in,
                              void* d_out, int out_size)
{
    const float* x  = (const float*)d_in[0];
    const float* Wq = (const float*)d_in[1];
    const float* bq = (const float*)d_in[2];
    const float* Wk = (const float*)d_in[3];
    const float* bk = (const float*)d_in[4];
    const float* Wv = (const float*)d_in[5];
    const float* bv = (const float*)d_in[6];
    const float* Wo = (const float*)d_in[7];
    const float* bo = (const float*)d_in[8];
    float* out = (float*)d_out;

    cudaFuncSetAttribute(gemm_mp<3, 0>, cudaFuncAttributeMaxDynamicSharedMemorySize, SMEM_BYTES);
    cudaFuncSetAttribute(gemm_mp<3, 1>, cudaFuncAttributeMaxDynamicSharedMemorySize, SMEM_BYTES);
    cudaFuncSetAttribute(gemm_mp<3, 2>, cudaFuncAttributeMaxDynamicSharedMemorySize, SMEM_BYTES);
    cudaFuncSetAttribute(gemm_mp<2, 3>, cudaFuncAttributeMaxDynamicSharedMemorySize, SMEM_BYTES);
    cudaFuncSetAttribute(gemm_mp<2, 0>, cudaFuncAttributeMaxDynamicSharedMemorySize, SMEM_BYTES);

#define SYM(ptr, sym) void* ptr##_v; cudaGetSymbolAddress(&ptr##_v, sym); \
    float* ptr = (float*)ptr##_v
    SYM(xh, g_xh);  SYM(xl, g_xl);
    SYM(wh, g_wh);  SYM(wl, g_wl);
    SYM(qh, g_qh);  SYM(ql, g_ql);
    SYM(kh, g_kh);  SYM(kl, g_kl);
    SYM(vTh, g_vTh); SYM(vTl, g_vTl);
    SYM(sS, g_s);
    SYM(pP, g_p);
    SYM(oO, g_o);
#undef SYM

    const int WSZ = DIMN * DIMN;
    float* Wqh = wh + 0 * WSZ; float* Wql = wl + 0 * WSZ;
    float* Wkh = wh + 1 * WSZ; float* Wkl = wl + 1 * WSZ;
    float* Wvh = wh + 2 * WSZ; float* Wvl = wl + 2 * WSZ;
    float* Woh = wh + 3 * WSZ; float* Wol = wl + 3 * WSZ;

    // splits of external inputs
    split_kernel<<<(MR * DIMN / 4 + 255) / 256, 256>>>(x,  xh,  xl,  MR * DIMN / 4);
    split_kernel<<<(WSZ / 4 + 255) / 256, 256>>>(Wq, Wqh, Wql, WSZ / 4);
    split_kernel<<<(WSZ / 4 + 255) / 256, 256>>>(Wk, Wkh, Wkl, WSZ / 4);
    split_kernel<<<(WSZ / 4 + 255) / 256, 256>>>(Wv, Wvh, Wvl, WSZ / 4);
    split_kernel<<<(WSZ / 4 + 255) / 256, 256>>>(Wo, Woh, Wol, WSZ / 4);

    const long long QS = (long long)SEQ * DIMN;  // q/k/v/o per-batch stride
    const long long SS = (long long)SEQ * SEQ;   // scores per-batch stride

    // projections (batch folded into M, strides 0): x3, accurate
    dim3 gp(DIMN / BN, MR / BM, 1);
    gemm_mp<3, 1><<<gp, NTHREADS, SMEM_BYTES>>>(xh, xl, Wqh, Wql, bq, qh, ql,
                                                MR, DIMN, DIMN, 0, 0, 0);
    gemm_mp<3, 1><<<gp, NTHREADS, SMEM_BYTES>>>(xh, xl, Wkh, Wkl, bk, kh, kl,
                                                MR, DIMN, DIMN, 0, 0, 0);
    gemm_mp<3, 2><<<gp, NTHREADS, SMEM_BYTES>>>(xh, xl, Wvh, Wvl, bv, vTh, vTl,
                                                MR, DIMN, DIMN, 0, 0, 0);

    // scores S[b] = Q[b] @ K[b]^T : x3 (error amplified via 0.1*relu)
    dim3 gs(SEQ / BN, SEQ / BM, BATCH);
    gemm_mp<3, 0><<<gs, NTHREADS, SMEM_BYTES>>>(qh, ql, kh, kl, nullptr, sS, nullptr,
                                                SEQ, SEQ, DIMN, QS, QS, SS);

    // theta + softmax -> tf32-rounded P
    theta_softmax<<<BATCH * SEQ, 256>>>(sS, pP);

    // O[b] = P[b] @ V[b] : x2 (P_hi*(V_hi+V_lo)), tf32-rounded O out
    dim3 gpv(DIMN / BN, SEQ / BM, BATCH);
    gemm_mp<2, 3><<<gpv, NTHREADS, SMEM_BYTES>>>(pP, pP, vTh, vTl, nullptr, oO, nullptr,
                                                 SEQ, DIMN, SEQ, SS,
                                                 (long long)DIMN * SEQ, QS);

    // out = O @ Wo^T + bo : x2 (O_hi*(W_hi+W_lo))
    gemm_mp<2, 0><<<gp, NTHREADS, SMEM_BYTES>>>(oO, oO, Woh, Wol, bo, out, nullptr,
                                                MR, DIMN, DIMN, 0, 0, 0);
}

// round 9
// speedup vs baseline: 1.7358x; 1.7358x over previous
#include <cuda_runtime.h>
#include <cuda_fp16.h>
#include <cstdint>

// ---------------- problem constants ----------------
#define SEQ    2048
#define DIMN   1024
#define BATCH  2
#define MR     4096            // BATCH*SEQ

// ---------------- GEMM tiling ----------------
#define BM 128
#define BN 128
#define BK 32                  // 32 halves; rows packed [hi 64B | lo 64B] = 128B
#define NTHREADS 256

#define TILEB  (BM * 128)              // 16384 B per operand tile (hi+lo packed)
#define STAGE  (2 * TILEB)             // A tile + B tile = 32768 B
#define NSTAGE 3
#define SMEM_BYTES (NSTAGE * STAGE)    // 98304 B

#define PV_SCALE 1024.0f               // P stored as fp16 * 2^10
#define PV_INV   (1.0f / 1024.0f)

// ---------------- scratch (__device__ globals; no allocs allowed) ----------------
static __device__ __half g_xh[MR * DIMN],  g_xl[MR * DIMN];
static __device__ __half g_wh[4][DIMN * DIMN], g_wl[4][DIMN * DIMN]; // q,k,v,o
static __device__ __half g_qh[MR * DIMN],  g_ql[MR * DIMN];
static __device__ __half g_kh[MR * DIMN],  g_kl[MR * DIMN];
static __device__ __half g_vTh[MR * DIMN], g_vTl[MR * DIMN];        // [B][D][S]
static __device__ float  g_s[BATCH * SEQ * SEQ];
static __device__ __half g_p[BATCH * SEQ * SEQ];                    // fp16, *1024
static __device__ __half g_o[MR * DIMN];                            // fp16 O

// ---------------- helpers ----------------
__device__ __forceinline__ uint32_t smem_u32(const void* p) {
    uint32_t a;
    asm("{ .reg .u64 t; cvta.to.shared.u64 t, %1; cvt.u32.u64 %0, t; }"
        : "=r"(a) : "l"(p));
    return a;
}

__device__ __forceinline__ void cp16(uint32_t saddr, const void* g) {
    asm volatile("cp.async.cg.shared.global [%0], [%1], 16;"
                 :: "r"(saddr), "l"(g) : "memory");
}

__device__ __forceinline__ void ldsm4(uint32_t* r, uint32_t addr) {
    asm volatile("ldmatrix.sync.aligned.m8n8.x4.shared.b16 {%0,%1,%2,%3}, [%4];"
                 : "=r"(r[0]), "=r"(r[1]), "=r"(r[2]), "=r"(r[3])
                 : "r"(addr));
}

__device__ __forceinline__ void mma_f16(float* d, const uint32_t* a,
                                        uint32_t b0, uint32_t b1) {
    asm volatile(
        "mma.sync.aligned.m16n8k16.row.col.f32.f16.f16.f32 "
        "{%0,%1,%2,%3}, {%4,%5,%6,%7}, {%8,%9}, {%0,%1,%2,%3};"
        : "+f"(d[0]), "+f"(d[1]), "+f"(d[2]), "+f"(d[3])
        : "r"(a[0]), "r"(a[1]), "r"(a[2]), "r"(a[3]), "r"(b0), "r"(b1));
}

__device__ __forceinline__ uint32_t sw128(uint32_t x) {
    return x ^ ((x >> 3) & 0x70);   // 128B-row xor swizzle
}

__device__ __forceinline__ __half2 split_pair(float v0, float v1, __half2& lo) {
    __half h0 = __float2half_rn(v0);
    __half h1 = __float2half_rn(v1);
    lo = __halves2half2(__float2half_rn(v0 - __half2float(h0)),
                        __float2half_rn(v1 - __half2float(h1)));
    return __halves2half2(h0, h1);
}

// ----------------------------------------------------------------------------
// Multi-pass fp16 GEMM via mma.sync m16n8k16:  C[M,N] = A[M,K] @ B[N,K]^T
// NPASS = 3: A = Ah+Al, B = Bh+Bl, terms hh + lh + hl (fp16x3 ~ fp32)
// NPASS = 2: A = Ah only,          terms hh + hl      (A-lo dropped)
// EPI: 0 = plain fp32 store (+optional bias)        (QK scores, final output)
//      1 = split store hi/lo fp16 (+optional bias)  (q/k projections)
//      2 = split fp16 TRANSPOSED [b][n][t] (+bias)  (v projection -> v^T)
//      3 = fp16 store of acc * PV_INV               (PV -> O, undo P scaling)
// Lo halves live at sw128(raw + 64): pre-swizzle offset, XOR stays in-row.
// Byte layout identical to the verified fp32/BK16 kernel (32 halves = 64B).
// ----------------------------------------------------------------------------
template <int NPASS, int EPI>
__global__ void __launch_bounds__(NTHREADS, 1)
gemm_mp(const __half* __restrict__ Ah, const __half* __restrict__ Al,
        const __half* __restrict__ Bh, const __half* __restrict__ Bl,
        const float* __restrict__ bias,
        void* __restrict__ C0v, void* __restrict__ C1v,
        int M, int N, int K,
        long long sA, long long sB, long long sC)
{
    extern __shared__ char dsmem[];
    const uint32_t sbase = smem_u32(dsmem);

    const int tid  = threadIdx.x;
    const int lane = tid & 31;
    const int wid  = tid >> 5;
    const int wm   = wid >> 2;        // 0..1 (m warp row)
    const int wn   = wid & 3;         // 0..3 (n warp col)

    const int m0 = blockIdx.y * BM;
    const int n0 = blockIdx.x * BN;
    const int bz = blockIdx.z;

    const __half* pAh = Ah + (long long)bz * sA;
    const __half* pAl = Al + (long long)bz * sA;
    const __half* pBh = Bh + (long long)bz * sB;
    const __half* pBl = Bl + (long long)bz * sB;

    // ---- cp.async slots: 512 16B hi-chunks per tile; each thread owns 2
    uint32_t c_hi[2];   // swizzled smem offset of hi chunk
    uint32_t c_lo[2];   // swizzled smem offset of lo chunk (raw + 64)
    int      a_g[2];    // gmem half offset (A)
    int      b_g[2];    // gmem half offset (B)
#pragma unroll
    for (int j = 0; j < 2; j++) {
        int c   = tid + j * NTHREADS;    // 0..511
        int row = c >> 2;                // 0..127
        int cc  = c & 3;                 // 16B chunk within 64B half
        uint32_t raw = (uint32_t)(row * 128 + cc * 16);
        c_hi[j] = sw128(raw);
        c_lo[j] = sw128(raw + 64);
        a_g[j]  = (m0 + row) * K + cc * 8;   // 8 halves per 16B chunk
        b_g[j]  = (n0 + row) * K + cc * 8;
    }

    auto load_tile = [&](int kt, int s) {
        const int k0 = kt * BK;
        const uint32_t stA = sbase + (uint32_t)s * STAGE;
        const uint32_t stB = stA + TILEB;
#pragma unroll
        for (int j = 0; j < 2; j++) {
            cp16(stA + c_hi[j], pAh + a_g[j] + k0);
            if (NPASS == 3)
                cp16(stA + c_lo[j], pAl + a_g[j] + k0);
            cp16(stB + c_hi[j], pBh + b_g[j] + k0);
            cp16(stB + c_lo[j], pBl + b_g[j] + k0);
        }
        asm volatile("cp.async.commit_group;" ::: "memory");
    };

    // ---- ldmatrix address components (b16-native; same byte math as before)
    const int piece = lane >> 3;
    const int pr    = lane & 7;

    int a_row[4];
#pragma unroll
    for (int mt = 0; mt < 4; mt++)
        a_row[mt] = (wm * 64 + mt * 16 + ((piece & 1) << 3) + pr) * 128;
    int b_row[2];
#pragma unroll
    for (int nt2 = 0; nt2 < 2; nt2++)
        b_row[nt2] = (wn * 32 + nt2 * 16 + ((piece >> 1) << 3) + pr) * 128;
    const int a_ch = (piece >> 1) * 16;   // k8-15 selector; +ks*32; raw+64 lo
    const int b_ch = (piece & 1) * 16;

    float acc[4][4][4];
#pragma unroll
    for (int i = 0; i < 4; i++)
#pragma unroll
        for (int j = 0; j < 4; j++)
#pragma unroll
            for (int r = 0; r < 4; r++) acc[i][j][r] = 0.0f;

    const int KT = K / BK;
    load_tile(0, 0);
    load_tile(1, 1);

    int s = 0, sp = 2;
    for (int kt = 0; kt < KT; kt++) {
        if (kt + 1 < KT)
            asm volatile("cp.async.wait_group 1;" ::: "memory");
        else
            asm volatile("cp.async.wait_group 0;" ::: "memory");
        __syncthreads();
        if (kt + 2 < KT) {
            load_tile(kt + 2, sp);
            if (++sp == NSTAGE) sp = 0;
        }

        const uint32_t stA = sbase + (uint32_t)s * STAGE;
        const uint32_t stB = stA + TILEB;
        if (++s == NSTAGE) s = 0;

#pragma unroll
        for (int ks = 0; ks < 2; ks++) {      // each ks = k16
            uint32_t fAh[4][4], fAl[4][4];
#pragma unroll
            for (int mt = 0; mt < 4; mt++) {
                uint32_t raw = (uint32_t)(a_row[mt] + ks * 32 + a_ch);
                ldsm4(fAh[mt], stA + sw128(raw));
                if (NPASS == 3) ldsm4(fAl[mt], stA + sw128(raw + 64));
            }
            uint32_t fBh[2][4], fBl[2][4];
#pragma unroll
            for (int nt2 = 0; nt2 < 2; nt2++) {
                uint32_t raw = (uint32_t)(b_row[nt2] + ks * 32 + b_ch);
                ldsm4(fBh[nt2], stB + sw128(raw));
                ldsm4(fBl[nt2], stB + sw128(raw + 64));
            }
#pragma unroll
            for (int mt = 0; mt < 4; mt++) {
#pragma unroll
                for (int nt = 0; nt < 4; nt++) {
                    const int nt2 = nt >> 1, hsel = (nt & 1) * 2;
                    float* d = acc[mt][nt];
                    mma_f16(d, fAh[mt], fBh[nt2][hsel], fBh[nt2][hsel + 1]);
                    if (NPASS == 3)
                        mma_f16(d, fAl[mt], fBh[nt2][hsel], fBh[nt2][hsel + 1]);
                    mma_f16(d, fAh[mt], fBl[nt2][hsel], fBl[nt2][hsel + 1]);
                }
            }
        }
    }

    // ---- epilogue
    const int rbase = m0 + wm * 64 + (lane >> 2);
    const int cbase = n0 + wn * 32 + (lane & 3) * 2;

#pragma unroll
    for (int mt = 0; mt < 4; mt++) {
#pragma unroll
        for (int nt = 0; nt < 4; nt++) {
            const float* d = acc[mt][nt];
            const int col = cbase + nt * 8;
            const long long r0 = rbase + mt * 16;
            const long long r1 = r0 + 8;
            float b0f = 0.0f, b1f = 0.0f;
            if (bias) { b0f = bias[col]; b1f = bias[col + 1]; }

            if (EPI == 0) {
                float* C = (float*)C0v + (long long)bz * sC;
                *reinterpret_cast<float2*>(&C[r0 * N + col]) =
                    make_float2(d[0] + b0f, d[1] + b1f);
                *reinterpret_cast<float2*>(&C[r1 * N + col]) =
                    make_float2(d[2] + b0f, d[3] + b1f);
            } else if (EPI == 1) {
                __half* Ch = (__half*)C0v + (long long)bz * sC;
                __half* Cl = (__half*)C1v + (long long)bz * sC;
                __half2 l0, l1;
                __half2 h0 = split_pair(d[0] + b0f, d[1] + b1f, l0);
                __half2 h1 = split_pair(d[2] + b0f, d[3] + b1f, l1);
                *reinterpret_cast<__half2*>(&Ch[r0 * N + col]) = h0;
                *reinterpret_cast<__half2*>(&Ch[r1 * N + col]) = h1;
                *reinterpret_cast<__half2*>(&Cl[r0 * N + col]) = l0;
                *reinterpret_cast<__half2*>(&Cl[r1 * N + col]) = l1;
            } else if (EPI == 2) {  // v^T split store, layout [b][n][t]
                __half* Ch = (__half*)C0v;
                __half* Cl = (__half*)C1v;
#pragma unroll
                for (int e = 0; e < 4; e++) {
                    const long long mr = (e < 2) ? r0 : r1;
                    const int n = col + (e & 1);
                    const float v = d[e] + ((e & 1) ? b1f : b0f);
                    const long long bb = mr >> 11;      // SEQ rows per batch
                    const long long t  = mr & 2047;
                    const __half h = __float2half_rn(v);
                    const long long idx = (bb * DIMN + n) * SEQ + t;
                    Ch[idx] = h;
                    Cl[idx] = __float2half_rn(v - __half2float(h));
                }
            } else {  // EPI == 3: fp16 store of acc * PV_INV (undo P scaling)
                __half* C = (__half*)C0v + (long long)bz * sC;
                *reinterpret_cast<__half2*>(&C[r0 * N + col]) =
                    __halves2half2(__float2half_rn(d[0] * PV_INV),
                                   __float2half_rn(d[1] * PV_INV));
                *reinterpret_cast<__half2*>(&C[r1 * N + col]) =
                    __halves2half2(__float2half_rn(d[2] * PV_INV),
                                   __float2half_rn(d[3] * PV_INV));
            }
        }
    }
}

// ----------------------------------------------------------------------------
// fp16 hi/lo split of external inputs
// ----------------------------------------------------------------------------
__global__ void __launch_bounds__(256)
split_kernel(const float* __restrict__ src, __half* __restrict__ hi,
             __half* __restrict__ lo, int n4)
{
    const int i = blockIdx.x * 256 + threadIdx.x;
    if (i < n4) {
        float4 v = reinterpret_cast<const float4*>(src)[i];
        __half2 l01, l23;
        __half2 h01 = split_pair(v.x, v.y, l01);
        __half2 h23 = split_pair(v.z, v.w, l23);
        reinterpret_cast<__half2*>(hi)[2 * i]     = h01;
        reinterpret_cast<__half2*>(hi)[2 * i + 1] = h23;
        reinterpret_cast<__half2*>(lo)[2 * i]     = l01;
        reinterpret_cast<__half2*>(lo)[2 * i + 1] = l23;
    }
}

// ----------------------------------------------------------------------------
// theta + softmax; emits fp16 probabilities scaled by 1024 (PV epilogue
// divides back). theta = 0.5 + 0.2*sigmoid(x) + 0.15*tanh(x) + 0.1*relu(x)
// ----------------------------------------------------------------------------
__global__ void __launch_bounds__(256)
theta_softmax(const float* __restrict__ S, __half* __restrict__ P)
{
    const long long ro = (long long)blockIdx.x * SEQ;
    const int tid  = threadIdx.x;
    const int lane = tid & 31;
    const int wid  = tid >> 5;
    __shared__ float red[8];

    float th[8];
    float mx = -1e30f;
#pragma unroll
    for (int j = 0; j < 8; j++) {
        float x = S[ro + tid + j * 256];
        float sg = 1.0f / (1.0f + __expf(-x));
        float t;
        asm("tanh.approx.f32 %0, %1;" : "=f"(t) : "f"(x));
        float v = 0.5f + 0.2f * sg + 0.15f * t + 0.1f * fmaxf(x, 0.0f);
        th[j] = v;
        mx = fmaxf(mx, v);
    }
#pragma unroll
    for (int o = 16; o > 0; o >>= 1)
        mx = fmaxf(mx, __shfl_xor_sync(0xFFFFFFFFu, mx, o));
    if (lane == 0) red[wid] = mx;
    __syncthreads();
    mx = red[0];
#pragma unroll
    for (int w = 1; w < 8; w++) mx = fmaxf(mx, red[w]);
    __syncthreads();

    float sum = 0.0f;
#pragma unroll
    for (int j = 0; j < 8; j++) {
        float e = __expf(th[j] - mx);
        th[j] = e;
        sum += e;
    }
#pragma unroll
    for (int o = 16; o > 0; o >>= 1)
        sum += __shfl_xor_sync(0xFFFFFFFFu, sum, o);
    if (lane == 0) red[wid] = sum;
    __syncthreads();
    sum = red[0];
#pragma unroll
    for (int w = 1; w < 8; w++) sum += red[w];

    const float inv = PV_SCALE / sum;
#pragma unroll
    for (int j = 0; j < 8; j++)
        P[ro + tid + j * 256] = __float2half_rn(th[j] * inv);
}

// ----------------------------------------------------------------------------
// launch — inputs: x, Wq, bq, Wk, bk, Wv, bv, Wo, bo
// ----------------------------------------------------------------------------
extern "C" void kernel_launch(void* const* d_in, const int* in_sizes, int n_in,
                              void* d_out, int out_size)
{
    const float* x  = (const float*)d_in[0];
    const float* Wq = (const float*)d_in[1];
    const float* bq = (const float*)d_in[2];
    const float* Wk = (const float*)d_in[3];
    const float* bk = (const float*)d_in[4];
    const float* Wv = (const float*)d_in[5];
    const float* bv = (const float*)d_in[6];
    const float* Wo = (const float*)d_in[7];
    const float* bo = (const float*)d_in[8];
    float* out = (float*)d_out;

    cudaFuncSetAttribute(gemm_mp<3, 0>, cudaFuncAttributeMaxDynamicSharedMemorySize, SMEM_BYTES);
    cudaFuncSetAttribute(gemm_mp<3, 1>, cudaFuncAttributeMaxDynamicSharedMemorySize, SMEM_BYTES);
    cudaFuncSetAttribute(gemm_mp<3, 2>, cudaFuncAttributeMaxDynamicSharedMemorySize, SMEM_BYTES);
    cudaFuncSetAttribute(gemm_mp<2, 3>, cudaFuncAttributeMaxDynamicSharedMemorySize, SMEM_BYTES);
    cudaFuncSetAttribute(gemm_mp<2, 0>, cudaFuncAttributeMaxDynamicSharedMemorySize, SMEM_BYTES);

#define SYM(ptr, ty, sym) void* ptr##_v; cudaGetSymbolAddress(&ptr##_v, sym); \
    ty* ptr = (ty*)ptr##_v
    SYM(xh, __half, g_xh);  SYM(xl, __half, g_xl);
    SYM(wh, __half, g_wh);  SYM(wl, __half, g_wl);
    SYM(qh, __half, g_qh);  SYM(ql, __half, g_ql);
    SYM(kh, __half, g_kh);  SYM(kl, __half, g_kl);
    SYM(vTh, __half, g_vTh); SYM(vTl, __half, g_vTl);
    SYM(sS, float, g_s);
    SYM(pP, __half, g_p);
    SYM(oO, __half, g_o);
#undef SYM

    const int WSZ = DIMN * DIMN;
    __half* Wqh = wh + 0 * WSZ; __half* Wql = wl + 0 * WSZ;
    __half* Wkh = wh + 1 * WSZ; __half* Wkl = wl + 1 * WSZ;
    __half* Wvh = wh + 2 * WSZ; __half* Wvl = wl + 2 * WSZ;
    __half* Woh = wh + 3 * WSZ; __half* Wol = wl + 3 * WSZ;

    // splits of external inputs
    split_kernel<<<(MR * DIMN / 4 + 255) / 256, 256>>>(x,  xh,  xl,  MR * DIMN / 4);
    split_kernel<<<(WSZ / 4 + 255) / 256, 256>>>(Wq, Wqh, Wql, WSZ / 4);
    split_kernel<<<(WSZ / 4 + 255) / 256, 256>>>(Wk, Wkh, Wkl, WSZ / 4);
    split_kernel<<<(WSZ / 4 + 255) / 256, 256>>>(Wv, Wvh, Wvl, WSZ / 4);
    split_kernel<<<(WSZ / 4 + 255) / 256, 256>>>(Wo, Woh, Wol, WSZ / 4);

    const long long QS = (long long)SEQ * DIMN;  // q/k/v/o per-batch stride
    const long long SS = (long long)SEQ * SEQ;   // scores per-batch stride

    // projections (batch folded into M, strides 0): x3, accurate
    dim3 gp(DIMN / BN, MR / BM, 1);
    gemm_mp<3, 1><<<gp, NTHREADS, SMEM_BYTES>>>(xh, xl, Wqh, Wql, bq, qh, ql,
                                                MR, DIMN, DIMN, 0, 0, 0);
    gemm_mp<3, 1><<<gp, NTHREADS, SMEM_BYTES>>>(xh, xl, Wkh, Wkl, bk, kh, kl,
                                                MR, DIMN, DIMN, 0, 0, 0);
    gemm_mp<3, 2><<<gp, NTHREADS, SMEM_BYTES>>>(xh, xl, Wvh, Wvl, bv, vTh, vTl,
                                                MR, DIMN, DIMN, 0, 0, 0);

    // scores S[b] = Q[b] @ K[b]^T : x3 (error amplified via 0.1*relu)
    dim3 gs(SEQ / BN, SEQ / BM, BATCH);
    gemm_mp<3, 0><<<gs, NTHREADS, SMEM_BYTES>>>(qh, ql, kh, kl, nullptr, sS, nullptr,
                                                SEQ, SEQ, DIMN, QS, QS, SS);

    // theta + softmax -> fp16 P (scaled x1024)
    theta_softmax<<<BATCH * SEQ, 256>>>(sS, pP);

    // O[b] = P[b] @ V[b] : x2 (P*(V_hi+V_lo)), fp16 O out, /1024 in epilogue
    dim3 gpv(DIMN / BN, SEQ / BM, BATCH);
    gemm_mp<2, 3><<<gpv, NTHREADS, SMEM_BYTES>>>(pP, pP, vTh, vTl, nullptr, oO, nullptr,
                                                 SEQ, DIMN, SEQ, SS,
                                                 (long long)DIMN * SEQ, QS);

    // out = O @ Wo^T + bo : x2 (O_hi*(W_hi+W_lo))
    gemm_mp<2, 0><<<gp, NTHREADS, SMEM_BYTES>>>(oO, oO, Woh, Wol, bo, out, nullptr,
                                                MR, DIMN, DIMN, 0, 0, 0);
}